// round 16
// baseline (speedup 1.0000x reference)
#include <cuda_runtime.h>
#include <cuda_fp16.h>
#include <math.h>
#include <stdint.h>

#define HID   2048
#define NB    2
#define SQ    2048
#define NHEAD 16
#define HD    128
#define MROWS (NB * SQ)        /* 4096 */
#define NW    (HID * HID)      /* 4194304 */
#define KDIM  2048

/* ---------------- scratch (device globals; no allocation allowed) -------- */
__device__ __half g_Wf[4][NW];          /* weights, single fp16             */
__device__ __half g_Xf[MROWS * HID];    /* activations, single fp16         */
__device__ __half g_Af[MROWS * HID];    /* attn output, single fp16         */
__device__ __half g_Qf[MROWS * HID];    /* Q fp16                           */
__device__ __half g_Kf[MROWS * HID];    /* K fp16                           */
__device__ __half g_Vf[MROWS * HID];    /* V fp16 [b,s,h,d]                 */
__device__ __half g_VT[MROWS * HID];    /* V fp16, transposed [b,h,d,s]     */

__device__ __forceinline__ uint32_t smem_u32(const void* p) {
    uint32_t a;
    asm("{ .reg .u64 t; cvta.to.shared.u64 t, %1; cvt.u32.u64 %0, t; }"
        : "=r"(a) : "l"(p));
    return a;
}
__device__ __forceinline__ void ldm_x4(uint32_t* r, uint32_t addr) {
    asm volatile("ldmatrix.sync.aligned.m8n8.x4.shared.b16 {%0,%1,%2,%3}, [%4];"
                 : "=r"(r[0]), "=r"(r[1]), "=r"(r[2]), "=r"(r[3]) : "r"(addr));
}
__device__ __forceinline__ void mma_f16(float* d, const uint32_t* a,
                                        uint32_t b0, uint32_t b1) {
    asm volatile("mma.sync.aligned.m16n8k16.row.col.f32.f16.f16.f32 "
                 "{%0,%1,%2,%3},{%4,%5,%6,%7},{%8,%9},{%0,%1,%2,%3};"
                 : "+f"(d[0]), "+f"(d[1]), "+f"(d[2]), "+f"(d[3])
                 : "r"(a[0]), "r"(a[1]), "r"(a[2]), "r"(a[3]), "r"(b0), "r"(b1));
}
__device__ __forceinline__ uint2 cvt4h(float4 v) {
    __half2 h0 = __float22half2_rn(make_float2(v.x, v.y));
    __half2 h1 = __float22half2_rn(make_float2(v.z, v.w));
    return make_uint2(*(uint32_t*)&h0, *(uint32_t*)&h1);
}
__device__ __forceinline__ uint32_t pack_h(float a, float b) {
    __half2 h = __float22half2_rn(make_float2(a, b));
    return *(uint32_t*)&h;
}
__device__ __forceinline__ uint32_t ex2_h2(float a, float b) {
    uint32_t t = pack_h(a, b), r;
    asm("ex2.approx.f16x2 %0, %1;" : "=r"(r) : "r"(t));
    return r;
}
__device__ __forceinline__ void cp16(uint32_t smem, const void* g) {
    asm volatile("cp.async.cg.shared.global [%0], [%1], 16;"
                 :: "r"(smem), "l"(g) : "memory");
}
__device__ __forceinline__ void cp_commit() {
    asm volatile("cp.async.commit_group;" ::: "memory");
}
template <int N>
__device__ __forceinline__ void cp_wait() {
    asm volatile("cp.async.wait_group %0;" :: "n"(N) : "memory");
}

/* ---------------- weight reconstruction -> single fp16 ------------------- */
__global__ void build_weights(const float* __restrict__ cpq,
                              const float* __restrict__ cpk,
                              const float* __restrict__ cpv,
                              const float* __restrict__ cpo,
                              int ncp) {
    int i = blockIdx.x * 256 + threadIdx.x;
    if (i >= NW) return;
    const float dT = 1.0f / (float)(NW - 1);
    const float dX = 1.0f / (float)(ncp - 1);
    float t = (float)i * dT;
    int j = (int)((double)t * (double)(ncp - 1));
    if (j > ncp - 2) j = ncp - 2;
    if (j < 0) j = 0;
    while (j < ncp - 2 && (float)(j + 1) * dX <= t) j++;
    while (j > 0 && (float)j * dX > t) j--;
    float x0 = (float)j * dX;
    float x1 = (float)(j + 1) * dX;
    float f  = (t - x0) / (x1 - x0);
    const float* cps[4] = {cpq, cpk, cpv, cpo};
#pragma unroll
    for (int w = 0; w < 4; w++) {
        float a = cps[w][j];
        g_Wf[w][i] = __float2half_rn(fmaf(cps[w][j + 1] - a, f, a));
    }
}

/* ---------------- convert hidden_states -> single fp16 ------------------- */
__global__ void split_x(const float* __restrict__ x) {
    int i = blockIdx.x * 256 + threadIdx.x;
    if (i >= MROWS * HID / 4) return;
    float4 v = *(const float4*)(x + 4 * (size_t)i);
    *(uint2*)(g_Xf + 4 * (size_t)i) = cvt4h(v);
}

/* ---------------- V fp16 [b,s,h,d] -> VT fp16 [b,h,d,s] ------------------ */
__global__ void vtrans(const __half* __restrict__ V) {
    __shared__ __half t[32][33];
    const int tx = threadIdx.x, ty = threadIdx.y;      /* 32 x 8 */
    const int s0 = blockIdx.x * 32, d0 = blockIdx.y * 32;
    const int bh = blockIdx.z;
    const int b = bh >> 4, h = bh & 15;
#pragma unroll
    for (int k = 0; k < 4; k++) {
        int srow = s0 + ty + 8 * k;
        t[ty + 8 * k][tx] = V[(size_t)(b * SQ + srow) * HID + h * HD + d0 + tx];
    }
    __syncthreads();
#pragma unroll
    for (int k = 0; k < 4; k++) {
        int drow = d0 + ty + 8 * k;
        g_VT[(size_t)(bh * HD + drow) * SQ + s0 + tx] = t[tx][ty + 8 * k];
    }
}

/* == fp16 HMMA GEMM: C = A*B^T.  CTA 128x128, 256 thr, KC=64 ============= */
#define KC      64
#define NCHUNK  (KDIM / KC)
#define SA      72
#define OFF_A   0
#define OFF_B   (128 * SA)
#define STG_HW  (2 * 128 * SA)
#define STG_B   (STG_HW * 2)            /* 36864 B                          */
#define GEMM_SMEM (2 * STG_B)           /* 73728 B                          */

__global__ void __launch_bounds__(256, 2) gemm_hmma(const __half* __restrict__ A,
                                                    const __half* __restrict__ Bbase,
                                                    __half* __restrict__ o16a,
                                                    __half* __restrict__ o16b,
                                                    __half* __restrict__ o16c,
                                                    float* __restrict__ o32,
                                                    int fused) {
    extern __shared__ char shg[];
    const uint32_t sb = smem_u32(shg);
    const int tid = threadIdx.x;
    const int lane = tid & 31, wid = tid >> 5;
    const int warp_m = wid >> 2;
    const int warp_n = wid & 3;
    const int m0 = blockIdx.y * 128, n0 = blockIdx.x * 128;
    const int z = fused ? (int)blockIdx.z : 3;
    const __half* B = fused ? (Bbase + (size_t)z * NW) : Bbase;
    __half* out16 = (z == 0) ? o16a : (z == 1) ? o16b : (z == 2) ? o16c : (__half*)0;

    const int rL = tid >> 3;
    const int cL = (tid & 7) << 3;
    const __half* gA = A + (size_t)(m0 + rL) * KDIM + cL;
    const __half* gB = B + (size_t)(n0 + rL) * KDIM + cL;
    uint32_t dA[4], dB[4];
#pragma unroll
    for (int p = 0; p < 4; p++) {
        dA[p] = sb + (uint32_t)((rL + 32 * p) * SA + cL) * 2;
        dB[p] = dA[p] + (uint32_t)OFF_B * 2;
    }

    float acc[4][4][4];
#pragma unroll
    for (int i = 0; i < 4; i++)
#pragma unroll
        for (int j = 0; j < 4; j++)
#pragma unroll
            for (int q = 0; q < 4; q++) acc[i][j][q] = 0.0f;

    const int rowA = lane & 15, colA8 = (lane >= 16) ? 8 : 0;
    const int rowB = (lane & 7) + ((lane >= 16) ? 8 : 0);
    const int colB8 = (lane & 8) ? 8 : 0;
    const uint32_t aoff = (uint32_t)((warp_m * 64 + rowA) * SA + colA8) * 2;
    const uint32_t boff = (uint32_t)((warp_n * 32 + rowB) * SA + colB8) * 2;

    {
#pragma unroll
        for (int p = 0; p < 4; p++) {
            cp16(dA[p], gA + (size_t)(32 * p) * KDIM);
            cp16(dB[p], gB + (size_t)(32 * p) * KDIM);
        }
        cp_commit();
    }

    for (int c = 0; c < NCHUNK; c++) {
        cp_wait<0>();
        __syncthreads();
        if (c + 1 < NCHUNK) {
            const uint32_t st = ((c + 1) & 1) * STG_B;
            const int kc = (c + 1) * KC;
#pragma unroll
            for (int p = 0; p < 4; p++) {
                cp16(dA[p] + st, gA + (size_t)(32 * p) * KDIM + kc);
                cp16(dB[p] + st, gB + (size_t)(32 * p) * KDIM + kc);
            }
            cp_commit();
        }

        const uint32_t stg = sb + (c & 1) * STG_B;
        const uint32_t tA = stg + OFF_A * 2, tB = stg + OFF_B * 2;
#pragma unroll
        for (int ks = 0; ks < 4; ks++) {
            const uint32_t ksoff = (uint32_t)(ks * 16) * 2;
            uint32_t ah[4][4];
#pragma unroll
            for (int mt = 0; mt < 4; mt++)
                ldm_x4(ah[mt], tA + aoff + ksoff + (uint32_t)(mt * 16 * SA) * 2);
#pragma unroll
            for (int g = 0; g < 2; g++) {
                uint32_t bb[4];
                ldm_x4(bb, tB + boff + ksoff + (uint32_t)(g * 16 * SA) * 2);
#pragma unroll
                for (int mt = 0; mt < 4; mt++) {
                    mma_f16(acc[mt][2 * g],     ah[mt], bb[0], bb[1]);
                    mma_f16(acc[mt][2 * g + 1], ah[mt], bb[2], bb[3]);
                }
            }
        }
    }

    const int rowg = lane >> 2, colg = (lane & 3) * 2;
    if (out16) {
#pragma unroll
        for (int mt = 0; mt < 4; mt++) {
#pragma unroll
            for (int nt = 0; nt < 4; nt++) {
                int r = m0 + warp_m * 64 + mt * 16 + rowg;
                int cc = n0 + warp_n * 32 + nt * 8 + colg;
                *(uint32_t*)(out16 + (size_t)r * KDIM + cc) =
                    pack_h(acc[mt][nt][0], acc[mt][nt][1]);
                *(uint32_t*)(out16 + (size_t)(r + 8) * KDIM + cc) =
                    pack_h(acc[mt][nt][2], acc[mt][nt][3]);
            }
        }
    } else {
#pragma unroll
        for (int mt = 0; mt < 4; mt++) {
#pragma unroll
            for (int nt = 0; nt < 4; nt++) {
                int r = m0 + warp_m * 64 + mt * 16 + rowg;
                int cc = n0 + warp_n * 32 + nt * 8 + colg;
                *(float2*)(o32 + (size_t)r * KDIM + cc) =
                    make_float2(acc[mt][nt][0], acc[mt][nt][1]);
                *(float2*)(o32 + (size_t)(r + 8) * KDIM + cc) =
                    make_float2(acc[mt][nt][2], acc[mt][nt][3]);
            }
        }
    }
}

/* ========== fp16 HMMA causal flash attention, 2 CTA/SM ==================== */
#define FKS 136
#define FVS 72
#define OFF_Q  0
#define OFF_K0 (128 * FKS)
#define OFF_V0 (OFF_K0 + 64 * FKS)
#define KVSTG  (64 * FKS + 128 * FVS)
#define FL_SMEM ((128 * FKS + 2 * KVSTG) * 2)   /* 106496 B -> 2 CTAs/SM    */

__global__ void __launch_bounds__(256, 2) flash_hmma(const __half* __restrict__ Qf,
                                                     const __half* __restrict__ Kf,
                                                     const __half* __restrict__ VT) {
    extern __shared__ char shf[];
    const uint32_t sb = smem_u32(shf);
    const int tid = threadIdx.x, lane = tid & 31, wid = tid >> 5;
    const int qb = (int)gridDim.x - 1 - (int)blockIdx.x;
    const int h = blockIdx.y, b = blockIdx.z;
    const int q0 = qb * 128;
    const int wm0 = wid * 16;
    const float scale = 0.08838834764831845f;
    const float L2E = 1.4426950408889634f;

    const __half* Qg = Qf + (size_t)(b * SQ + q0) * HID + h * HD;
#pragma unroll
    for (int it = 0; it < 8; it++) {
        int idx = tid + it * 256;
        int r = idx >> 4, c8 = (idx & 15) << 3;
        cp16(sb + (uint32_t)(OFF_Q + r * FKS + c8) * 2, Qg + (size_t)r * HID + c8);
    }

    const __half* Kg0 = Kf + (size_t)(b * SQ) * HID + h * HD;
    const __half* Vg0 = VT + (size_t)((b * NHEAD + h) * HD) * SQ;

    {
#pragma unroll
        for (int it = 0; it < 4; it++) {
            int u = tid + it * 256;
            int r = u >> 4, c8 = (u & 15) << 3;
            cp16(sb + (uint32_t)(OFF_K0 + r * FKS + c8) * 2, Kg0 + (size_t)r * HID + c8);
        }
#pragma unroll
        for (int it = 0; it < 4; it++) {
            int u = tid + it * 256;
            int d = u >> 3, c8 = (u & 7) << 3;
            cp16(sb + (uint32_t)(OFF_V0 + d * FVS + c8) * 2, Vg0 + (size_t)d * SQ + c8);
        }
        cp_commit();
    }

    const uint32_t aBase = sb + 2u * (OFF_Q + (wm0 + (lane & 15)) * FKS + ((lane >> 4) << 3));
    const int krow = (lane & 7) + ((lane >> 4) << 3);
    uint32_t kBase[2], vBase[2];
#pragma unroll
    for (int bu = 0; bu < 2; bu++) {
        kBase[bu] = sb + 2u * (OFF_K0 + bu * KVSTG + krow * FKS + (lane & 8));
        vBase[bu] = sb + 2u * (OFF_V0 + bu * KVSTG + krow * FVS + (lane & 8));
    }

    float acc_o[16][4];
#pragma unroll
    for (int i = 0; i < 16; i++)
#pragma unroll
        for (int j = 0; j < 4; j++) acc_o[i][j] = 0.0f;
    float m0r = -1e30f, m1r = -1e30f, l0r = 0.0f, l1r = 0.0f;

    const int kb_max = 2 * qb + 1;
    const int r0g = q0 + wm0 + (lane >> 2);
    const int r1g = r0g + 8;

    for (int kb = 0; kb <= kb_max; kb++) {
        const int k0 = kb * 64;
        cp_wait<0>();
        __syncthreads();

        if (kb < kb_max) {
            const int kn = (kb + 1) * 64;
            const uint32_t bo = (uint32_t)(((kb + 1) & 1) * KVSTG) * 2;
#pragma unroll
            for (int it = 0; it < 4; it++) {
                int u = tid + it * 256;
                int r = u >> 4, c8 = (u & 15) << 3;
                cp16(sb + (uint32_t)(OFF_K0 + r * FKS + c8) * 2 + bo,
                     Kg0 + (size_t)(kn + r) * HID + c8);
            }
#pragma unroll
            for (int it = 0; it < 4; it++) {
                int u = tid + it * 256;
                int d = u >> 3, c8 = (u & 7) << 3;
                cp16(sb + (uint32_t)(OFF_V0 + d * FVS + c8) * 2 + bo,
                     Vg0 + (size_t)d * SQ + kn + c8);
            }
            cp_commit();
        }

        if (k0 > q0 + wm0) continue;
        const uint32_t kB = kBase[kb & 1], vB = vBase[kb & 1];

        float accs[8][4];
#pragma unroll
        for (int i = 0; i < 8; i++)
#pragma unroll
            for (int j = 0; j < 4; j++) accs[i][j] = 0.0f;
#pragma unroll
        for (int ks = 0; ks < 8; ks++) {
            uint32_t qh[4];
            ldm_x4(qh, aBase + ks * 32);
            uint32_t kk4[4][4];
#pragma unroll
            for (int ng = 0; ng < 4; ng++)
                ldm_x4(kk4[ng], kB + (uint32_t)(ng * 16 * FKS) * 2 + ks * 32);
#pragma unroll
            for (int ng = 0; ng < 4; ng++) {
                mma_f16(accs[2 * ng],     qh, kk4[ng][0], kk4[ng][1]);
                mma_f16(accs[2 * ng + 1], qh, kk4[ng][2], kk4[ng][3]);
            }
        }

#pragma unroll
        for (int nt = 0; nt < 8; nt++) {
            int cb = k0 + nt * 8 + (lane & 3) * 2;
            accs[nt][0] = accs[nt][0] * scale + ((cb     > r0g) ? -1e9f : 0.0f);
            accs[nt][1] = accs[nt][1] * scale + ((cb + 1 > r0g) ? -1e9f : 0.0f);
            accs[nt][2] = accs[nt][2] * scale + ((cb     > r1g) ? -1e9f : 0.0f);
            accs[nt][3] = accs[nt][3] * scale + ((cb + 1 > r1g) ? -1e9f : 0.0f);
        }

        float mx0 = -1e30f, mx1 = -1e30f;
#pragma unroll
        for (int nt = 0; nt < 8; nt++) {
            mx0 = fmaxf(mx0, fmaxf(accs[nt][0], accs[nt][1]));
            mx1 = fmaxf(mx1, fmaxf(accs[nt][2], accs[nt][3]));
        }
        mx0 = fmaxf(mx0, __shfl_xor_sync(0xffffffffu, mx0, 1));
        mx0 = fmaxf(mx0, __shfl_xor_sync(0xffffffffu, mx0, 2));
        mx1 = fmaxf(mx1, __shfl_xor_sync(0xffffffffu, mx1, 1));
        mx1 = fmaxf(mx1, __shfl_xor_sync(0xffffffffu, mx1, 2));
        float mn0 = fmaxf(m0r, mx0), mn1 = fmaxf(m1r, mx1);
        float al0 = __expf(m0r - mn0), al1 = __expf(m1r - mn1);
        m0r = mn0; m1r = mn1;

        uint32_t pe[8][2];
        float rs0 = 0.0f, rs1 = 0.0f;
        const float c0 = -mn0 * L2E, c1 = -mn1 * L2E;
#pragma unroll
        for (int nt = 0; nt < 8; nt++) {
            pe[nt][0] = ex2_h2(fmaf(accs[nt][0], L2E, c0), fmaf(accs[nt][1], L2E, c0));
            pe[nt][1] = ex2_h2(fmaf(accs[nt][2], L2E, c1), fmaf(accs[nt][3], L2E, c1));
            float2 f01 = __half22float2(*(__half2*)&pe[nt][0]);
            float2 f23 = __half22float2(*(__half2*)&pe[nt][1]);
            rs0 += f01.x + f01.y;
            rs1 += f23.x + f23.y;
        }
        rs0 += __shfl_xor_sync(0xffffffffu, rs0, 1);
        rs0 += __shfl_xor_sync(0xffffffffu, rs0, 2);
        rs1 += __shfl_xor_sync(0xffffffffu, rs1, 1);
        rs1 += __shfl_xor_sync(0xffffffffu, rs1, 2);
        l0r = l0r * al0 + rs0;
        l1r = l1r * al1 + rs1;
#pragma unroll
        for (int i = 0; i < 16; i++) {
            acc_o[i][0] *= al0; acc_o[i][1] *= al0;
            acc_o[i][2] *= al1; acc_o[i][3] *= al1;
        }

        uint32_t ph[4][4];
#pragma unroll
        for (int kk = 0; kk < 4; kk++) {
            ph[kk][0] = pe[2 * kk][0];
            ph[kk][1] = pe[2 * kk][1];
            ph[kk][2] = pe[2 * kk + 1][0];
            ph[kk][3] = pe[2 * kk + 1][1];
        }

#pragma unroll
        for (int kk = 0; kk < 4; kk++) {
#pragma unroll
            for (int gb = 0; gb < 8; gb += 4) {
                uint32_t vt[4][4];
#pragma unroll
                for (int g = 0; g < 4; g++)
                    ldm_x4(vt[g], vB + (uint32_t)((gb + g) * 16 * FVS) * 2 + kk * 32);
#pragma unroll
                for (int g = 0; g < 4; g++) {
                    mma_f16(acc_o[2 * (gb + g)],     ph[kk], vt[g][0], vt[g][1]);
                    mma_f16(acc_o[2 * (gb + g) + 1], ph[kk], vt[g][2], vt[g][3]);
                }
            }
        }
    }

    float inv0 = 1.0f / l0r, inv1 = 1.0f / l1r;
    size_t base0 = (size_t)(b * SQ + r0g) * HID + h * HD;
    size_t base1 = base0 + (size_t)8 * HID;
#pragma unroll
    for (int nto = 0; nto < 16; nto++) {
        int c = nto * 8 + (lane & 3) * 2;
        *(uint32_t*)(g_Af + base0 + c) = pack_h(acc_o[nto][0] * inv0, acc_o[nto][1] * inv0);
        *(uint32_t*)(g_Af + base1 + c) = pack_h(acc_o[nto][2] * inv1, acc_o[nto][3] * inv1);
    }
}

/* ---------------- launcher ---------------------------------------------- */
extern "C" void kernel_launch(void* const* d_in, const int* in_sizes, int n_in,
                              void* d_out, int out_size) {
    (void)n_in; (void)out_size;
    const float* x   = (const float*)d_in[0];
    const float* cpq = (const float*)d_in[1];
    const float* cpk = (const float*)d_in[2];
    const float* cpv = (const float*)d_in[3];
    const float* cpo = (const float*)d_in[4];
    float* out = (float*)d_out;
    int ncp = in_sizes[1];

    __half *pWf, *pXf, *pAf, *pQf, *pKf, *pVf, *pVT;
    cudaGetSymbolAddress((void**)&pWf, g_Wf);
    cudaGetSymbolAddress((void**)&pXf, g_Xf);
    cudaGetSymbolAddress((void**)&pAf, g_Af);
    cudaGetSymbolAddress((void**)&pQf, g_Qf);
    cudaGetSymbolAddress((void**)&pKf, g_Kf);
    cudaGetSymbolAddress((void**)&pVf, g_Vf);
    cudaGetSymbolAddress((void**)&pVT, g_VT);

    build_weights<<<(NW + 255) / 256, 256>>>(cpq, cpk, cpv, cpo, ncp);
    split_x<<<(MROWS * HID / 4 + 255) / 256, 256>>>(x);

    cudaFuncSetAttribute(gemm_hmma, cudaFuncAttributeMaxDynamicSharedMemorySize,
                         GEMM_SMEM);
    /* fused QKV: z=0 -> Qf, z=1 -> Kf, z=2 -> Vf (all fp16) */
    gemm_hmma<<<dim3(HID / 128, MROWS / 128, 3), 256, GEMM_SMEM>>>(
        pXf, pWf, pQf, pKf, pVf, (float*)0, 1);

    vtrans<<<dim3(SQ / 32, HD / 32, NB * NHEAD), dim3(32, 8)>>>(pVf);

    cudaFuncSetAttribute(flash_hmma, cudaFuncAttributeMaxDynamicSharedMemorySize,
                         FL_SMEM);
    flash_hmma<<<dim3(SQ / 128, NHEAD, NB), 256, FL_SMEM>>>(pQf, pKf, pVT);

    /* O-projection: fp32 out */
    gemm_hmma<<<dim3(HID / 128, MROWS / 128, 1), 256, GEMM_SMEM>>>(
        pAf, pWf + 3 * (size_t)NW, (__half*)0, (__half*)0, (__half*)0, out, 0);
}

// round 17
// speedup vs baseline: 1.0177x; 1.0177x over previous
#include <cuda_runtime.h>
#include <cuda_fp16.h>
#include <math.h>
#include <stdint.h>

#define HID   2048
#define NB    2
#define SQ    2048
#define NHEAD 16
#define HD    128
#define MROWS (NB * SQ)        /* 4096 */
#define NW    (HID * HID)      /* 4194304 */
#define KDIM  2048

/* ---------------- scratch (device globals; no allocation allowed) -------- */
__device__ __half g_Wf[4][NW];          /* weights, single fp16             */
__device__ __half g_Xf[MROWS * HID];    /* activations, single fp16         */
__device__ __half g_Af[MROWS * HID];    /* attn output, single fp16         */
__device__ __half g_Qf[MROWS * HID];    /* Q fp16                           */
__device__ __half g_Kf[MROWS * HID];    /* K fp16                           */
__device__ __half g_Vf[MROWS * HID];    /* V fp16 [b,s,h,d]                 */
__device__ __half g_VT[MROWS * HID];    /* V fp16, transposed [b,h,d,s]     */

__device__ __forceinline__ uint32_t smem_u32(const void* p) {
    uint32_t a;
    asm("{ .reg .u64 t; cvta.to.shared.u64 t, %1; cvt.u32.u64 %0, t; }"
        : "=r"(a) : "l"(p));
    return a;
}
__device__ __forceinline__ void ldm_x4(uint32_t* r, uint32_t addr) {
    asm volatile("ldmatrix.sync.aligned.m8n8.x4.shared.b16 {%0,%1,%2,%3}, [%4];"
                 : "=r"(r[0]), "=r"(r[1]), "=r"(r[2]), "=r"(r[3]) : "r"(addr));
}
__device__ __forceinline__ void mma_f16(float* d, const uint32_t* a,
                                        uint32_t b0, uint32_t b1) {
    asm volatile("mma.sync.aligned.m16n8k16.row.col.f32.f16.f16.f32 "
                 "{%0,%1,%2,%3},{%4,%5,%6,%7},{%8,%9},{%0,%1,%2,%3};"
                 : "+f"(d[0]), "+f"(d[1]), "+f"(d[2]), "+f"(d[3])
                 : "r"(a[0]), "r"(a[1]), "r"(a[2]), "r"(a[3]), "r"(b0), "r"(b1));
}
__device__ __forceinline__ uint2 cvt4h(float4 v) {
    __half2 h0 = __float22half2_rn(make_float2(v.x, v.y));
    __half2 h1 = __float22half2_rn(make_float2(v.z, v.w));
    return make_uint2(*(uint32_t*)&h0, *(uint32_t*)&h1);
}
__device__ __forceinline__ uint32_t pack_h(float a, float b) {
    __half2 h = __float22half2_rn(make_float2(a, b));
    return *(uint32_t*)&h;
}
__device__ __forceinline__ uint32_t ex2_h2(float a, float b) {
    uint32_t t = pack_h(a, b), r;
    asm("ex2.approx.f16x2 %0, %1;" : "=r"(r) : "r"(t));
    return r;
}
__device__ __forceinline__ void cp16(uint32_t smem, const void* g) {
    asm volatile("cp.async.cg.shared.global [%0], [%1], 16;"
                 :: "r"(smem), "l"(g) : "memory");
}
__device__ __forceinline__ void cp_commit() {
    asm volatile("cp.async.commit_group;" ::: "memory");
}
template <int N>
__device__ __forceinline__ void cp_wait() {
    asm volatile("cp.async.wait_group %0;" :: "n"(N) : "memory");
}

/* ---------------- weight reconstruction -> single fp16 ------------------- */
__global__ void build_weights(const float* __restrict__ cpq,
                              const float* __restrict__ cpk,
                              const float* __restrict__ cpv,
                              const float* __restrict__ cpo,
                              int ncp) {
    int i = blockIdx.x * 256 + threadIdx.x;
    if (i >= NW) return;
    const float dT = 1.0f / (float)(NW - 1);
    const float dX = 1.0f / (float)(ncp - 1);
    float t = (float)i * dT;
    int j = (int)((double)t * (double)(ncp - 1));
    if (j > ncp - 2) j = ncp - 2;
    if (j < 0) j = 0;
    while (j < ncp - 2 && (float)(j + 1) * dX <= t) j++;
    while (j > 0 && (float)j * dX > t) j--;
    float x0 = (float)j * dX;
    float x1 = (float)(j + 1) * dX;
    float f  = (t - x0) / (x1 - x0);
    const float* cps[4] = {cpq, cpk, cpv, cpo};
#pragma unroll
    for (int w = 0; w < 4; w++) {
        float a = cps[w][j];
        g_Wf[w][i] = __float2half_rn(fmaf(cps[w][j + 1] - a, f, a));
    }
}

/* ---------------- convert hidden_states -> single fp16 ------------------- */
__global__ void split_x(const float* __restrict__ x) {
    int i = blockIdx.x * 256 + threadIdx.x;
    if (i >= MROWS * HID / 4) return;
    float4 v = *(const float4*)(x + 4 * (size_t)i);
    *(uint2*)(g_Xf + 4 * (size_t)i) = cvt4h(v);
}

/* ---------------- V fp16 [b,s,h,d] -> VT fp16 [b,h,d,s] ------------------ */
__global__ void vtrans(const __half* __restrict__ V) {
    __shared__ __half t[32][33];
    const int tx = threadIdx.x, ty = threadIdx.y;      /* 32 x 8 */
    const int s0 = blockIdx.x * 32, d0 = blockIdx.y * 32;
    const int bh = blockIdx.z;
    const int b = bh >> 4, h = bh & 15;
#pragma unroll
    for (int k = 0; k < 4; k++) {
        int srow = s0 + ty + 8 * k;
        t[ty + 8 * k][tx] = V[(size_t)(b * SQ + srow) * HID + h * HD + d0 + tx];
    }
    __syncthreads();
#pragma unroll
    for (int k = 0; k < 4; k++) {
        int drow = d0 + ty + 8 * k;
        g_VT[(size_t)(bh * HD + drow) * SQ + s0 + tx] = t[tx][ty + 8 * k];
    }
}

/* == fp16 HMMA GEMM: C = A*B^T.  CTA 128x128, 256 thr, KC=64 ============= */
#define KC      64
#define NCHUNK  (KDIM / KC)
#define SA      72
#define OFF_A   0
#define OFF_B   (128 * SA)
#define STG_HW  (2 * 128 * SA)
#define STG_B   (STG_HW * 2)            /* 36864 B                          */
#define GEMM_SMEM (2 * STG_B)           /* 73728 B                          */

__global__ void __launch_bounds__(256, 2) gemm_hmma(const __half* __restrict__ A,
                                                    const __half* __restrict__ Bbase,
                                                    __half* __restrict__ o16a,
                                                    __half* __restrict__ o16b,
                                                    __half* __restrict__ o16c,
                                                    float* __restrict__ o32,
                                                    int fused) {
    extern __shared__ char shg[];
    const uint32_t sb = smem_u32(shg);
    const int tid = threadIdx.x;
    const int lane = tid & 31, wid = tid >> 5;
    const int warp_m = wid >> 2;
    const int warp_n = wid & 3;
    const int m0 = blockIdx.y * 128, n0 = blockIdx.x * 128;
    const int z = fused ? (int)blockIdx.z : 3;
    const __half* B = fused ? (Bbase + (size_t)z * NW) : Bbase;
    __half* out16 = (z == 0) ? o16a : (z == 1) ? o16b : (z == 2) ? o16c : (__half*)0;

    const int rL = tid >> 3;
    const int cL = (tid & 7) << 3;
    const __half* gA = A + (size_t)(m0 + rL) * KDIM + cL;
    const __half* gB = B + (size_t)(n0 + rL) * KDIM + cL;
    uint32_t dA[4], dB[4];
#pragma unroll
    for (int p = 0; p < 4; p++) {
        dA[p] = sb + (uint32_t)((rL + 32 * p) * SA + cL) * 2;
        dB[p] = dA[p] + (uint32_t)OFF_B * 2;
    }

    float acc[4][4][4];
#pragma unroll
    for (int i = 0; i < 4; i++)
#pragma unroll
        for (int j = 0; j < 4; j++)
#pragma unroll
            for (int q = 0; q < 4; q++) acc[i][j][q] = 0.0f;

    const int rowA = lane & 15, colA8 = (lane >= 16) ? 8 : 0;
    const int rowB = (lane & 7) + ((lane >= 16) ? 8 : 0);
    const int colB8 = (lane & 8) ? 8 : 0;
    const uint32_t aoff = (uint32_t)((warp_m * 64 + rowA) * SA + colA8) * 2;
    const uint32_t boff = (uint32_t)((warp_n * 32 + rowB) * SA + colB8) * 2;

    {
#pragma unroll
        for (int p = 0; p < 4; p++) {
            cp16(dA[p], gA + (size_t)(32 * p) * KDIM);
            cp16(dB[p], gB + (size_t)(32 * p) * KDIM);
        }
        cp_commit();
    }

    for (int c = 0; c < NCHUNK; c++) {
        cp_wait<0>();
        __syncthreads();
        if (c + 1 < NCHUNK) {
            const uint32_t st = ((c + 1) & 1) * STG_B;
            const int kc = (c + 1) * KC;
#pragma unroll
            for (int p = 0; p < 4; p++) {
                cp16(dA[p] + st, gA + (size_t)(32 * p) * KDIM + kc);
                cp16(dB[p] + st, gB + (size_t)(32 * p) * KDIM + kc);
            }
            cp_commit();
        }

        const uint32_t stg = sb + (c & 1) * STG_B;
        const uint32_t tA = stg + OFF_A * 2, tB = stg + OFF_B * 2;
#pragma unroll
        for (int ks = 0; ks < 4; ks++) {
            const uint32_t ksoff = (uint32_t)(ks * 16) * 2;
            uint32_t ah[4][4];
#pragma unroll
            for (int mt = 0; mt < 4; mt++)
                ldm_x4(ah[mt], tA + aoff + ksoff + (uint32_t)(mt * 16 * SA) * 2);
#pragma unroll
            for (int g = 0; g < 2; g++) {
                uint32_t bb[4];
                ldm_x4(bb, tB + boff + ksoff + (uint32_t)(g * 16 * SA) * 2);
#pragma unroll
                for (int mt = 0; mt < 4; mt++) {
                    mma_f16(acc[mt][2 * g],     ah[mt], bb[0], bb[1]);
                    mma_f16(acc[mt][2 * g + 1], ah[mt], bb[2], bb[3]);
                }
            }
        }
    }

    const int rowg = lane >> 2, colg = (lane & 3) * 2;
    if (out16) {
#pragma unroll
        for (int mt = 0; mt < 4; mt++) {
#pragma unroll
            for (int nt = 0; nt < 4; nt++) {
                int r = m0 + warp_m * 64 + mt * 16 + rowg;
                int cc = n0 + warp_n * 32 + nt * 8 + colg;
                *(uint32_t*)(out16 + (size_t)r * KDIM + cc) =
                    pack_h(acc[mt][nt][0], acc[mt][nt][1]);
                *(uint32_t*)(out16 + (size_t)(r + 8) * KDIM + cc) =
                    pack_h(acc[mt][nt][2], acc[mt][nt][3]);
            }
        }
    } else {
#pragma unroll
        for (int mt = 0; mt < 4; mt++) {
#pragma unroll
            for (int nt = 0; nt < 4; nt++) {
                int r = m0 + warp_m * 64 + mt * 16 + rowg;
                int cc = n0 + warp_n * 32 + nt * 8 + colg;
                *(float2*)(o32 + (size_t)r * KDIM + cc) =
                    make_float2(acc[mt][nt][0], acc[mt][nt][1]);
                *(float2*)(o32 + (size_t)(r + 8) * KDIM + cc) =
                    make_float2(acc[mt][nt][2], acc[mt][nt][3]);
            }
        }
    }
}

/* ========== fp16 HMMA causal flash attention (occ 1, full regs) ========== */
#define FKS 136
#define FVS 72
#define OFF_Q  0
#define OFF_K0 (128 * FKS)
#define OFF_V0 (OFF_K0 + 64 * FKS)
#define KVSTG  (64 * FKS + 128 * FVS)
#define FL_SMEM ((128 * FKS + 2 * KVSTG) * 2)   /* 106496 B                 */

__global__ void __launch_bounds__(256, 1) flash_hmma(const __half* __restrict__ Qf,
                                                     const __half* __restrict__ Kf,
                                                     const __half* __restrict__ VT) {
    extern __shared__ char shf[];
    const uint32_t sb = smem_u32(shf);
    const int tid = threadIdx.x, lane = tid & 31, wid = tid >> 5;
    const int qb = (int)gridDim.x - 1 - (int)blockIdx.x;
    const int h = blockIdx.y, b = blockIdx.z;
    const int q0 = qb * 128;
    const int wm0 = wid * 16;
    const float scale = 0.08838834764831845f;
    const float L2E = 1.4426950408889634f;

    const __half* Qg = Qf + (size_t)(b * SQ + q0) * HID + h * HD;
#pragma unroll
    for (int it = 0; it < 8; it++) {
        int idx = tid + it * 256;
        int r = idx >> 4, c8 = (idx & 15) << 3;
        cp16(sb + (uint32_t)(OFF_Q + r * FKS + c8) * 2, Qg + (size_t)r * HID + c8);
    }

    const __half* Kg0 = Kf + (size_t)(b * SQ) * HID + h * HD;
    const __half* Vg0 = VT + (size_t)((b * NHEAD + h) * HD) * SQ;

    {
#pragma unroll
        for (int it = 0; it < 4; it++) {
            int u = tid + it * 256;
            int r = u >> 4, c8 = (u & 15) << 3;
            cp16(sb + (uint32_t)(OFF_K0 + r * FKS + c8) * 2, Kg0 + (size_t)r * HID + c8);
        }
#pragma unroll
        for (int it = 0; it < 4; it++) {
            int u = tid + it * 256;
            int d = u >> 3, c8 = (u & 7) << 3;
            cp16(sb + (uint32_t)(OFF_V0 + d * FVS + c8) * 2, Vg0 + (size_t)d * SQ + c8);
        }
        cp_commit();
    }

    const uint32_t aBase = sb + 2u * (OFF_Q + (wm0 + (lane & 15)) * FKS + ((lane >> 4) << 3));
    const int krow = (lane & 7) + ((lane >> 4) << 3);
    uint32_t kBase[2], vBase[2];
#pragma unroll
    for (int bu = 0; bu < 2; bu++) {
        kBase[bu] = sb + 2u * (OFF_K0 + bu * KVSTG + krow * FKS + (lane & 8));
        vBase[bu] = sb + 2u * (OFF_V0 + bu * KVSTG + krow * FVS + (lane & 8));
    }

    float acc_o[16][4];
#pragma unroll
    for (int i = 0; i < 16; i++)
#pragma unroll
        for (int j = 0; j < 4; j++) acc_o[i][j] = 0.0f;
    float m0r = -1e30f, m1r = -1e30f, l0r = 0.0f, l1r = 0.0f;

    const int kb_max = 2 * qb + 1;
    const int r0g = q0 + wm0 + (lane >> 2);
    const int r1g = r0g + 8;

    for (int kb = 0; kb <= kb_max; kb++) {
        const int k0 = kb * 64;
        cp_wait<0>();
        __syncthreads();

        if (kb < kb_max) {
            const int kn = (kb + 1) * 64;
            const uint32_t bo = (uint32_t)(((kb + 1) & 1) * KVSTG) * 2;
#pragma unroll
            for (int it = 0; it < 4; it++) {
                int u = tid + it * 256;
                int r = u >> 4, c8 = (u & 15) << 3;
                cp16(sb + (uint32_t)(OFF_K0 + r * FKS + c8) * 2 + bo,
                     Kg0 + (size_t)(kn + r) * HID + c8);
            }
#pragma unroll
            for (int it = 0; it < 4; it++) {
                int u = tid + it * 256;
                int d = u >> 3, c8 = (u & 7) << 3;
                cp16(sb + (uint32_t)(OFF_V0 + d * FVS + c8) * 2 + bo,
                     Vg0 + (size_t)d * SQ + kn + c8);
            }
            cp_commit();
        }

        if (k0 > q0 + wm0) continue;
        const uint32_t kB = kBase[kb & 1], vB = vBase[kb & 1];

        float accs[8][4];
#pragma unroll
        for (int i = 0; i < 8; i++)
#pragma unroll
            for (int j = 0; j < 4; j++) accs[i][j] = 0.0f;
#pragma unroll
        for (int ks = 0; ks < 8; ks++) {
            uint32_t qh[4];
            ldm_x4(qh, aBase + ks * 32);
            uint32_t kk4[4][4];
#pragma unroll
            for (int ng = 0; ng < 4; ng++)
                ldm_x4(kk4[ng], kB + (uint32_t)(ng * 16 * FKS) * 2 + ks * 32);
#pragma unroll
            for (int ng = 0; ng < 4; ng++) {
                mma_f16(accs[2 * ng],     qh, kk4[ng][0], kk4[ng][1]);
                mma_f16(accs[2 * ng + 1], qh, kk4[ng][2], kk4[ng][3]);
            }
        }

#pragma unroll
        for (int nt = 0; nt < 8; nt++) {
            int cb = k0 + nt * 8 + (lane & 3) * 2;
            accs[nt][0] = accs[nt][0] * scale + ((cb     > r0g) ? -1e9f : 0.0f);
            accs[nt][1] = accs[nt][1] * scale + ((cb + 1 > r0g) ? -1e9f : 0.0f);
            accs[nt][2] = accs[nt][2] * scale + ((cb     > r1g) ? -1e9f : 0.0f);
            accs[nt][3] = accs[nt][3] * scale + ((cb + 1 > r1g) ? -1e9f : 0.0f);
        }

        float mx0 = -1e30f, mx1 = -1e30f;
#pragma unroll
        for (int nt = 0; nt < 8; nt++) {
            mx0 = fmaxf(mx0, fmaxf(accs[nt][0], accs[nt][1]));
            mx1 = fmaxf(mx1, fmaxf(accs[nt][2], accs[nt][3]));
        }
        mx0 = fmaxf(mx0, __shfl_xor_sync(0xffffffffu, mx0, 1));
        mx0 = fmaxf(mx0, __shfl_xor_sync(0xffffffffu, mx0, 2));
        mx1 = fmaxf(mx1, __shfl_xor_sync(0xffffffffu, mx1, 1));
        mx1 = fmaxf(mx1, __shfl_xor_sync(0xffffffffu, mx1, 2));
        float mn0 = fmaxf(m0r, mx0), mn1 = fmaxf(m1r, mx1);
        float al0 = __expf(m0r - mn0), al1 = __expf(m1r - mn1);
        m0r = mn0; m1r = mn1;

        uint32_t pe[8][2];
        float rs0 = 0.0f, rs1 = 0.0f;
        const float c0 = -mn0 * L2E, c1 = -mn1 * L2E;
#pragma unroll
        for (int nt = 0; nt < 8; nt++) {
            pe[nt][0] = ex2_h2(fmaf(accs[nt][0], L2E, c0), fmaf(accs[nt][1], L2E, c0));
            pe[nt][1] = ex2_h2(fmaf(accs[nt][2], L2E, c1), fmaf(accs[nt][3], L2E, c1));
            float2 f01 = __half22float2(*(__half2*)&pe[nt][0]);
            float2 f23 = __half22float2(*(__half2*)&pe[nt][1]);
            rs0 += f01.x + f01.y;
            rs1 += f23.x + f23.y;
        }
        rs0 += __shfl_xor_sync(0xffffffffu, rs0, 1);
        rs0 += __shfl_xor_sync(0xffffffffu, rs0, 2);
        rs1 += __shfl_xor_sync(0xffffffffu, rs1, 1);
        rs1 += __shfl_xor_sync(0xffffffffu, rs1, 2);
        l0r = l0r * al0 + rs0;
        l1r = l1r * al1 + rs1;
#pragma unroll
        for (int i = 0; i < 16; i++) {
            acc_o[i][0] *= al0; acc_o[i][1] *= al0;
            acc_o[i][2] *= al1; acc_o[i][3] *= al1;
        }

        uint32_t ph[4][4];
#pragma unroll
        for (int kk = 0; kk < 4; kk++) {
            ph[kk][0] = pe[2 * kk][0];
            ph[kk][1] = pe[2 * kk][1];
            ph[kk][2] = pe[2 * kk + 1][0];
            ph[kk][3] = pe[2 * kk + 1][1];
        }

#pragma unroll
        for (int kk = 0; kk < 4; kk++) {
#pragma unroll
            for (int gb = 0; gb < 8; gb += 4) {
                uint32_t vt[4][4];
#pragma unroll
                for (int g = 0; g < 4; g++)
                    ldm_x4(vt[g], vB + (uint32_t)((gb + g) * 16 * FVS) * 2 + kk * 32);
#pragma unroll
                for (int g = 0; g < 4; g++) {
                    mma_f16(acc_o[2 * (gb + g)],     ph[kk], vt[g][0], vt[g][1]);
                    mma_f16(acc_o[2 * (gb + g) + 1], ph[kk], vt[g][2], vt[g][3]);
                }
            }
        }
    }

    float inv0 = 1.0f / l0r, inv1 = 1.0f / l1r;
    size_t base0 = (size_t)(b * SQ + r0g) * HID + h * HD;
    size_t base1 = base0 + (size_t)8 * HID;
#pragma unroll
    for (int nto = 0; nto < 16; nto++) {
        int c = nto * 8 + (lane & 3) * 2;
        *(uint32_t*)(g_Af + base0 + c) = pack_h(acc_o[nto][0] * inv0, acc_o[nto][1] * inv0);
        *(uint32_t*)(g_Af + base1 + c) = pack_h(acc_o[nto][2] * inv1, acc_o[nto][3] * inv1);
    }
}

/* ---------------- launcher ---------------------------------------------- */
extern "C" void kernel_launch(void* const* d_in, const int* in_sizes, int n_in,
                              void* d_out, int out_size) {
    (void)n_in; (void)out_size;
    const float* x   = (const float*)d_in[0];
    const float* cpq = (const float*)d_in[1];
    const float* cpk = (const float*)d_in[2];
    const float* cpv = (const float*)d_in[3];
    const float* cpo = (const float*)d_in[4];
    float* out = (float*)d_out;
    int ncp = in_sizes[1];

    __half *pWf, *pXf, *pAf, *pQf, *pKf, *pVf, *pVT;
    cudaGetSymbolAddress((void**)&pWf, g_Wf);
    cudaGetSymbolAddress((void**)&pXf, g_Xf);
    cudaGetSymbolAddress((void**)&pAf, g_Af);
    cudaGetSymbolAddress((void**)&pQf, g_Qf);
    cudaGetSymbolAddress((void**)&pKf, g_Kf);
    cudaGetSymbolAddress((void**)&pVf, g_Vf);
    cudaGetSymbolAddress((void**)&pVT, g_VT);

    build_weights<<<(NW + 255) / 256, 256>>>(cpq, cpk, cpv, cpo, ncp);
    split_x<<<(MROWS * HID / 4 + 255) / 256, 256>>>(x);

    cudaFuncSetAttribute(gemm_hmma, cudaFuncAttributeMaxDynamicSharedMemorySize,
                         GEMM_SMEM);
    /* fused QKV: z=0 -> Qf, z=1 -> Kf, z=2 -> Vf (all fp16) */
    gemm_hmma<<<dim3(HID / 128, MROWS / 128, 3), 256, GEMM_SMEM>>>(
        pXf, pWf, pQf, pKf, pVf, (float*)0, 1);

    vtrans<<<dim3(SQ / 32, HD / 32, NB * NHEAD), dim3(32, 8)>>>(pVf);

    cudaFuncSetAttribute(flash_hmma, cudaFuncAttributeMaxDynamicSharedMemorySize,
                         FL_SMEM);
    flash_hmma<<<dim3(SQ / 128, NHEAD, NB), 256, FL_SMEM>>>(pQf, pKf, pVT);

    /* O-projection: fp32 out */
    gemm_hmma<<<dim3(HID / 128, MROWS / 128, 1), 256, GEMM_SMEM>>>(
        pAf, pWf + 3 * (size_t)NW, (__half*)0, (__half*)0, (__half*)0, out, 0);
}